// round 11
// baseline (speedup 1.0000x reference)
#include <cuda_runtime.h>
#include <math.h>

#define SS 512
#define NN 64
#define CC 512
#define QQ 256
#define VV 10
#define GG 2048
#define NB5 64
#define HTS2 516   // hts [n][k] stride
#define WTS3 40    // wts [k][gi] stride (32 gi + pad)
#define REDS 34    // red [n][gi] stride

__device__ float g_a0[SS * NN];
__device__ float g_a1[SS * NN];
__device__ float g_A[(size_t)NN * SS * QQ];
__device__ float g_queue[(size_t)QQ * NN * CC];
__device__ float g_xg[(size_t)QQ * NN * GG];
__device__ float g_gh[2 * NN * CC];               // h (tf32-rounded) [buf][n][k]
__device__ float g_hs[(size_t)QQ * NN * CC];
__device__ unsigned g_barcnt;

// ---------------- tf32 helpers ----------------
__device__ __forceinline__ float to_tf32(float x) {
    unsigned r;
    asm("cvt.rna.tf32.f32 %0, %1;" : "=r"(r) : "f"(x));
    return __uint_as_float(r);
}
__device__ __forceinline__ void mma_tf32(float& d0, float& d1, float& d2, float& d3,
                                         float a0, float a1, float a2, float a3,
                                         float b0, float b1) {
    asm volatile(
        "mma.sync.aligned.m16n8k8.row.col.f32.tf32.tf32.f32 "
        "{%0,%1,%2,%3},{%4,%5,%6,%7},{%8,%9},{%0,%1,%2,%3};"
        : "+f"(d0), "+f"(d1), "+f"(d2), "+f"(d3)
        : "r"(__float_as_uint(a0)), "r"(__float_as_uint(a1)),
          "r"(__float_as_uint(a2)), "r"(__float_as_uint(a3)),
          "r"(__float_as_uint(b0)), "r"(__float_as_uint(b1)));
}

// ---------------- K1: action softmax ----------------
__global__ void k1_actions(const float* __restrict__ memory,
                           const float* __restrict__ W_act,
                           const float* __restrict__ b_act) {
    int warp = blockIdx.x * (blockDim.x >> 5) + (threadIdx.x >> 5);
    int lane = threadIdx.x & 31;
    if (warp >= SS * NN) return;
    const float* row = memory + (size_t)warp * CC;
    float z0 = 0.f, z1 = 0.f;
    for (int c = lane; c < CC; c += 32) {
        float m = row[c];
        z0 += m * W_act[2 * c];
        z1 += m * W_act[2 * c + 1];
    }
#pragma unroll
    for (int o = 16; o; o >>= 1) {
        z0 += __shfl_down_sync(0xffffffffu, z0, o);
        z1 += __shfl_down_sync(0xffffffffu, z1, o);
    }
    if (lane == 0) {
        z0 += b_act[0]; z1 += b_act[1];
        float mx = fmaxf(z0, z1);
        float e0 = expf(z0 - mx), e1 = expf(z1 - mx);
        float inv = 1.f / (e0 + e1);
        g_a0[warp] = e0 * inv;
        g_a1[warp] = e1 * inv;
    }
}

// ---------------- K2: posvec recurrence ----------------
__global__ void k2_posvec() {
    if (blockIdx.x == 0 && threadIdx.x == 0) g_barcnt = 0u;
    int n = blockIdx.x;
    int q = threadIdx.x;
    __shared__ float sp[QQ];
    __shared__ float sa0[SS], sa1[SS];
    for (int s = q; s < SS; s += QQ) {
        sa0[s] = g_a0[s * NN + n];
        sa1[s] = g_a1[s * NN + n];
    }
    __syncthreads();
    float p = (q == 0) ? 1.f : 0.f;
    float* An = g_A + (size_t)n * SS * QQ;
    for (int s = 0; s < SS; s++) {
        float a0 = sa0[s], a1 = sa1[s];
        An[(size_t)s * QQ + q] = p * a1;
        sp[q] = p;
        __syncthreads();
        float prev = sp[(q + QQ - 1) & (QQ - 1)];
        __syncthreads();
        p = p * a0 + prev * a1;
    }
}

// ---------------- K3: queue via tf32 mma ----------------
__global__ void __launch_bounds__(256) k3_queue(const float* __restrict__ memory) {
    __shared__ float As[128 * 17];   // [q][s]
    __shared__ float Bs[64 * 17];    // [c][s]
    int n = blockIdx.z;
    int q0 = blockIdx.y * 128;
    int c0 = blockIdx.x * 64;
    int tid = threadIdx.x;
    int warp = tid >> 5, lane = tid & 31;
    int wm = warp >> 1, wn = warp & 1;
    int lr = lane >> 2, lc = lane & 3;

    float c[2][4][4];
#pragma unroll
    for (int a = 0; a < 2; a++)
#pragma unroll
        for (int b = 0; b < 4; b++)
#pragma unroll
            for (int d = 0; d < 4; d++) c[a][b][d] = 0.f;

    const float* Abase = g_A + (size_t)n * SS * QQ + q0;
    const float* Bbase = memory + (size_t)n * CC + c0;

    for (int s0 = 0; s0 < SS; s0 += 16) {
#pragma unroll
        for (int l = 0; l < 2; l++) {
            int f = tid + l * 256;
            int s = f >> 5, q4 = (f & 31) * 4;
            float4 v = *(const float4*)&Abase[(size_t)(s0 + s) * QQ + q4];
            As[(q4 + 0) * 17 + s] = to_tf32(v.x);
            As[(q4 + 1) * 17 + s] = to_tf32(v.y);
            As[(q4 + 2) * 17 + s] = to_tf32(v.z);
            As[(q4 + 3) * 17 + s] = to_tf32(v.w);
        }
        {
            int s = tid >> 4, c4 = (tid & 15) * 4;
            float4 v = *(const float4*)&Bbase[(size_t)(s0 + s) * NN * CC + c4];
            Bs[(c4 + 0) * 17 + s] = to_tf32(v.x);
            Bs[(c4 + 1) * 17 + s] = to_tf32(v.y);
            Bs[(c4 + 2) * 17 + s] = to_tf32(v.z);
            Bs[(c4 + 3) * 17 + s] = to_tf32(v.w);
        }
        __syncthreads();
#pragma unroll
        for (int ks = 0; ks < 2; ks++) {
            int k0 = ks * 8;
            float a[2][4];
#pragma unroll
            for (int tm = 0; tm < 2; tm++) {
                int row = wm * 32 + tm * 16 + lr;
                a[tm][0] = As[row * 17 + k0 + lc];
                a[tm][1] = As[(row + 8) * 17 + k0 + lc];
                a[tm][2] = As[row * 17 + k0 + lc + 4];
                a[tm][3] = As[(row + 8) * 17 + k0 + lc + 4];
            }
#pragma unroll
            for (int tn = 0; tn < 4; tn++) {
                int col = wn * 32 + tn * 8 + lr;
                float b0 = Bs[col * 17 + k0 + lc];
                float b1 = Bs[col * 17 + k0 + lc + 4];
#pragma unroll
                for (int tm = 0; tm < 2; tm++)
                    mma_tf32(c[tm][tn][0], c[tm][tn][1], c[tm][tn][2], c[tm][tn][3],
                             a[tm][0], a[tm][1], a[tm][2], a[tm][3], b0, b1);
            }
        }
        __syncthreads();
    }
#pragma unroll
    for (int tm = 0; tm < 2; tm++) {
#pragma unroll
        for (int tn = 0; tn < 4; tn++) {
            int cc = c0 + wn * 32 + tn * 8 + lc * 2;
            int r0 = q0 + wm * 32 + tm * 16 + lr;
            *(float2*)&g_queue[((size_t)r0 * NN + n) * CC + cc] =
                make_float2(c[tm][tn][0], c[tm][tn][1]);
            *(float2*)&g_queue[((size_t)(r0 + 8) * NN + n) * CC + cc] =
                make_float2(c[tm][tn][2], c[tm][tn][3]);
        }
    }
}

// ---------------- K4: xg = queue @ W_ih^T via tf32 mma.sync ----------------
__global__ void __launch_bounds__(256) k4_xgates(const float* __restrict__ W_ih,
                                                 const float* __restrict__ b_ih,
                                                 const float* __restrict__ b_hh) {
    __shared__ __align__(16) float As[128 * 20];
    __shared__ __align__(16) float Bs[128 * 20];
    int tid = threadIdx.x;
    int m0 = blockIdx.y * 128, g0 = blockIdx.x * 128;
    int warp = tid >> 5, lane = tid & 31;
    int wm = warp >> 1, wn = warp & 1;
    int lr = lane >> 2, lc = lane & 3;

    float c[2][8][4];
#pragma unroll
    for (int a = 0; a < 2; a++)
#pragma unroll
        for (int b = 0; b < 8; b++)
#pragma unroll
            for (int d = 0; d < 4; d++) c[a][b][d] = 0.f;

    int sr = tid >> 2;
    int sk = (tid & 3) * 4;
    const float* Ag = g_queue + (size_t)(m0 + sr) * CC + sk;
    const float* Bg = W_ih + (size_t)(g0 + sr) * CC + sk;

    float4 ra0 = *(const float4*)Ag;
    float4 ra1 = *(const float4*)(Ag + (size_t)64 * CC);
    float4 rb0 = *(const float4*)Bg;
    float4 rb1 = *(const float4*)(Bg + (size_t)64 * CC);

    for (int kt = 0; kt < 32; kt++) {
        *(float4*)&As[sr * 20 + sk] =
            make_float4(to_tf32(ra0.x), to_tf32(ra0.y), to_tf32(ra0.z), to_tf32(ra0.w));
        *(float4*)&As[(sr + 64) * 20 + sk] =
            make_float4(to_tf32(ra1.x), to_tf32(ra1.y), to_tf32(ra1.z), to_tf32(ra1.w));
        *(float4*)&Bs[sr * 20 + sk] =
            make_float4(to_tf32(rb0.x), to_tf32(rb0.y), to_tf32(rb0.z), to_tf32(rb0.w));
        *(float4*)&Bs[(sr + 64) * 20 + sk] =
            make_float4(to_tf32(rb1.x), to_tf32(rb1.y), to_tf32(rb1.z), to_tf32(rb1.w));
        __syncthreads();
        if (kt < 31) {
            int off = (kt + 1) * 16;
            ra0 = *(const float4*)(Ag + off);
            ra1 = *(const float4*)(Ag + (size_t)64 * CC + off);
            rb0 = *(const float4*)(Bg + off);
            rb1 = *(const float4*)(Bg + (size_t)64 * CC + off);
        }
#pragma unroll
        for (int s = 0; s < 2; s++) {
            int k0 = s * 8;
            float a[2][4];
#pragma unroll
            for (int tm = 0; tm < 2; tm++) {
                int row = wm * 32 + tm * 16 + lr;
                a[tm][0] = As[row * 20 + k0 + lc];
                a[tm][1] = As[(row + 8) * 20 + k0 + lc];
                a[tm][2] = As[row * 20 + k0 + lc + 4];
                a[tm][3] = As[(row + 8) * 20 + k0 + lc + 4];
            }
#pragma unroll
            for (int tn = 0; tn < 8; tn++) {
                int col = wn * 64 + tn * 8 + lr;
                float b0 = Bs[col * 20 + k0 + lc];
                float b1 = Bs[col * 20 + k0 + lc + 4];
#pragma unroll
                for (int tm = 0; tm < 2; tm++)
                    mma_tf32(c[tm][tn][0], c[tm][tn][1], c[tm][tn][2], c[tm][tn][3],
                             a[tm][0], a[tm][1], a[tm][2], a[tm][3], b0, b1);
            }
        }
        __syncthreads();
    }
#pragma unroll
    for (int tm = 0; tm < 2; tm++) {
#pragma unroll
        for (int tn = 0; tn < 8; tn++) {
            int g = g0 + wn * 64 + tn * 8 + lc * 2;
            float bv0 = b_ih[g] + b_hh[g];
            float bv1 = b_ih[g + 1] + b_hh[g + 1];
            int r0 = m0 + wm * 32 + tm * 16 + lr;
            float2 v0 = make_float2(c[tm][tn][0] + bv0, c[tm][tn][1] + bv1);
            float2 v1 = make_float2(c[tm][tn][2] + bv0, c[tm][tn][3] + bv1);
            *(float2*)&g_xg[(size_t)r0 * GG + g] = v0;
            *(float2*)&g_xg[(size_t)(r0 + 8) * GG + g] = v1;
        }
    }
}

// ---------------- K5: persistent LSTM (64 blocks, 8 c-cols each, A-reuse x4) ----------------
__device__ __forceinline__ float sigf(float x) { return 1.f / (1.f + expf(-x)); }

__device__ __forceinline__ void gridbar(unsigned target) {
    if (threadIdx.x == 0) {
        __threadfence();
        atomicAdd(&g_barcnt, 1u);
        while (*(volatile unsigned*)&g_barcnt < target) __nanosleep(32);
        __threadfence();
    }
    __syncthreads();
}

__global__ void __launch_bounds__(256, 1) k5_lstm(const float* __restrict__ W_hh) {
    extern __shared__ float sm[];
    float* hts = sm;                       // [64][HTS2]
    float* wts = sm + NN * HTS2;           // [512][WTS3], 32 gi cols
    float* red = wts + CC * WTS3;          // [64][REDS]  kh partials
    float* gsm = red + NN * REDS;          // [32][64]    gates [gi][n]
    int tid = threadIdx.x;
    int b = blockIdx.x;
    int c0 = b * 8;
    int wid = tid >> 5, lane = tid & 31;
    int mt = wid & 3;                      // m-tile: 16 n-rows
    int kh = wid >> 2;                     // K-half
    int gid = lane >> 2, tig = lane & 3;

    // preload W slice as tf32: wts[k][gi], gi = gate*8 + j
    {
        int gi = tid >> 3;                 // 0..31
        int gate = gi >> 3, j = gi & 7;
        const float* wrow = W_hh + (size_t)(gate * CC + c0 + j) * CC;
        int kc = (tid & 7) * 64;
#pragma unroll
        for (int u2 = 0; u2 < 16; u2++) {
            float4 v = *(const float4*)&wrow[kc + u2 * 4];
            wts[(kc + u2 * 4 + 0) * WTS3 + gi] = to_tf32(v.x);
            wts[(kc + u2 * 4 + 1) * WTS3 + gi] = to_tf32(v.y);
            wts[(kc + u2 * 4 + 2) * WTS3 + gi] = to_tf32(v.z);
            wts[(kc + u2 * 4 + 3) * WTS3 + gi] = to_tf32(v.w);
        }
    }
    if (tid < 64) {
        *(float4*)&g_gh[tid * CC + c0] = make_float4(0.f, 0.f, 0.f, 0.f);
        *(float4*)&g_gh[tid * CC + c0 + 4] = make_float4(0.f, 0.f, 0.f, 0.f);
    }
    __syncthreads();
    unsigned u = 1;
    gridbar(u * NB5); u++;

    float creg[8] = {0.f, 0.f, 0.f, 0.f, 0.f, 0.f, 0.f, 0.f};

    for (int step = 0; step < QQ; step++) {
        int par = step & 1;
        const float* hb = g_gh + par * (NN * CC);

        // prefetch this step's input gates (8 cols per gate)
        float xvf[4][8];
        if (tid < 64) {
            const float* xb = g_xg + ((size_t)step * NN + tid) * GG + c0;
#pragma unroll
            for (int g = 0; g < 4; g++) {
                float4 v0 = *(const float4*)&xb[g * 512];
                float4 v1 = *(const float4*)&xb[g * 512 + 4];
                xvf[g][0] = v0.x; xvf[g][1] = v0.y; xvf[g][2] = v0.z; xvf[g][3] = v0.w;
                xvf[g][4] = v1.x; xvf[g][5] = v1.y; xvf[g][6] = v1.z; xvf[g][7] = v1.w;
            }
        }
        // stage full h [64][512] into smem
#pragma unroll
        for (int it = 0; it < 32; it++) {
            int f = tid + it * 256;
            int n = f >> 7;
            int k4 = (f & 127) * 4;
            float4 v = __ldcg((const float4*)&hb[n * CC + k4]);
            *(float4*)&hts[n * HTS2 + k4] = v;
        }
        __syncthreads();

        // mma: warp (mt, kh) computes 16 rows x 32 gi over K/2, 4 indep accumulators
        float c[4][4];
#pragma unroll
        for (int nt = 0; nt < 4; nt++)
#pragma unroll
            for (int i = 0; i < 4; i++) c[nt][i] = 0.f;
        const float* Ab = &hts[(mt * 16) * HTS2 + kh * 256];
        const float* Bb = &wts[(kh * 256) * WTS3];
#pragma unroll 4
        for (int kc = 0; kc < 32; kc++) {
            int k0 = kc * 8;
            float a0 = Ab[gid * HTS2 + k0 + tig];
            float a1 = Ab[(gid + 8) * HTS2 + k0 + tig];
            float a2 = Ab[gid * HTS2 + k0 + tig + 4];
            float a3 = Ab[(gid + 8) * HTS2 + k0 + tig + 4];
#pragma unroll
            for (int nt = 0; nt < 4; nt++) {
                float b0 = Bb[(k0 + tig) * WTS3 + nt * 8 + gid];
                float b1 = Bb[(k0 + tig + 4) * WTS3 + nt * 8 + gid];
                mma_tf32(c[nt][0], c[nt][1], c[nt][2], c[nt][3],
                         a0, a1, a2, a3, b0, b1);
            }
        }
        if (kh == 1) {
#pragma unroll
            for (int nt = 0; nt < 4; nt++) {
                int n0 = mt * 16 + gid;
                int gi0 = nt * 8 + tig * 2;
                *(float2*)&red[n0 * REDS + gi0] = make_float2(c[nt][0], c[nt][1]);
                *(float2*)&red[(n0 + 8) * REDS + gi0] = make_float2(c[nt][2], c[nt][3]);
            }
        }
        __syncthreads();
        if (kh == 0) {
#pragma unroll
            for (int nt = 0; nt < 4; nt++) {
                int n0 = mt * 16 + gid;
                int gi0 = nt * 8 + tig * 2;
                float2 r0 = *(const float2*)&red[n0 * REDS + gi0];
                float2 r1 = *(const float2*)&red[(n0 + 8) * REDS + gi0];
                gsm[gi0 * 64 + n0] = c[nt][0] + r0.x;
                gsm[(gi0 + 1) * 64 + n0] = c[nt][1] + r0.y;
                gsm[gi0 * 64 + n0 + 8] = c[nt][2] + r1.x;
                gsm[(gi0 + 1) * 64 + n0 + 8] = c[nt][3] + r1.y;
            }
        }
        __syncthreads();

        // activation + h/c update (8 cols per n)
        if (tid < 64) {
            int nxt = (step + 1) & 1;
            float* ho = g_gh + nxt * (NN * CC) + tid * CC + c0;
            float* hsout = g_hs + ((size_t)step * NN + tid) * CC + c0;
            float hv[8];
#pragma unroll
            for (int j = 0; j < 8; j++) {
                float iv = gsm[(0 * 8 + j) * 64 + tid] + xvf[0][j];
                float fv = gsm[(1 * 8 + j) * 64 + tid] + xvf[1][j];
                float gv = gsm[(2 * 8 + j) * 64 + tid] + xvf[2][j];
                float ov = gsm[(3 * 8 + j) * 64 + tid] + xvf[3][j];
                float cc = sigf(fv) * creg[j] + sigf(iv) * tanhf(gv);
                creg[j] = cc;
                hv[j] = sigf(ov) * tanhf(cc);
            }
            *(float4*)&ho[0] = make_float4(to_tf32(hv[0]), to_tf32(hv[1]),
                                           to_tf32(hv[2]), to_tf32(hv[3]));
            *(float4*)&ho[4] = make_float4(to_tf32(hv[4]), to_tf32(hv[5]),
                                           to_tf32(hv[6]), to_tf32(hv[7]));
            *(float4*)&hsout[0] = make_float4(hv[0], hv[1], hv[2], hv[3]);
            *(float4*)&hsout[4] = make_float4(hv[4], hv[5], hv[6], hv[7]);
        }
        __syncthreads();
        gridbar(u * NB5); u++;
    }
}

// ---------------- K6: LayerNorm + decode ----------------
__global__ void k6_lndec(const float* __restrict__ gamma,
                         const float* __restrict__ beta,
                         const float* __restrict__ W_dec,
                         const float* __restrict__ b_dec,
                         float* __restrict__ out) {
    __shared__ float sW[CC * VV];
    __shared__ float sG[CC], sB[CC], sbd[VV];
    int tid = threadIdx.x;
    for (int i = tid; i < CC * VV; i += 256) sW[i] = W_dec[i];
    for (int i = tid; i < CC; i += 256) { sG[i] = gamma[i]; sB[i] = beta[i]; }
    if (tid < VV) sbd[tid] = b_dec[tid];
    __syncthreads();

    int warp = blockIdx.x * 8 + (tid >> 5);
    int lane = tid & 31;
    if (warp >= QQ * NN) return;
    const float* row = g_hs + (size_t)warp * CC;

    float x[16];
    float s = 0.f, s2 = 0.f;
#pragma unroll
    for (int t = 0; t < 4; t++) {
        float4 v = *(const float4*)&row[lane * 4 + t * 128];
        x[t * 4 + 0] = v.x; x[t * 4 + 1] = v.y; x[t * 4 + 2] = v.z; x[t * 4 + 3] = v.w;
        s += v.x + v.y + v.z + v.w;
        s2 += v.x * v.x + v.y * v.y + v.z * v.z + v.w * v.w;
    }
#pragma unroll
    for (int o = 16; o; o >>= 1) {
        s += __shfl_xor_sync(0xffffffffu, s, o);
        s2 += __shfl_xor_sync(0xffffffffu, s2, o);
    }
    float mu = s * (1.f / CC);
    float var = s2 * (1.f / CC) - mu * mu;
    float rs = rsqrtf(var + 1e-5f);

    float acc[VV];
#pragma unroll
    for (int v = 0; v < VV; v++) acc[v] = 0.f;
#pragma unroll
    for (int t = 0; t < 4; t++) {
#pragma unroll
        for (int e = 0; e < 4; e++) {
            int c = lane * 4 + t * 128 + e;
            float nv = (x[t * 4 + e] - mu) * rs * sG[c] + sB[c];
#pragma unroll
            for (int v = 0; v < VV; v++) acc[v] = fmaf(nv, sW[c * VV + v], acc[v]);
        }
    }
#pragma unroll
    for (int v = 0; v < VV; v++) {
        float a = acc[v];
#pragma unroll
        for (int o = 16; o; o >>= 1) a += __shfl_xor_sync(0xffffffffu, a, o);
        if (lane == 0) out[(size_t)warp * VV + v] = a + sbd[v];
    }
}

extern "C" void kernel_launch(void* const* d_in, const int* in_sizes, int n_in,
                              void* d_out, int out_size) {
    const float* memory = (const float*)d_in[0];
    const float* W_act  = (const float*)d_in[1];
    const float* b_act  = (const float*)d_in[2];
    const float* W_ih   = (const float*)d_in[3];
    const float* W_hh   = (const float*)d_in[4];
    const float* b_ih   = (const float*)d_in[5];
    const float* b_hh   = (const float*)d_in[6];
    const float* lng    = (const float*)d_in[7];
    const float* lnb    = (const float*)d_in[8];
    const float* W_dec  = (const float*)d_in[9];
    const float* b_dec  = (const float*)d_in[10];
    float* out = (float*)d_out;

    k1_actions<<<(SS * NN + 7) / 8, 256>>>(memory, W_act, b_act);
    k2_posvec<<<NN, QQ>>>();
    k3_queue<<<dim3(CC / 64, QQ / 128, NN), 256>>>(memory);
    k4_xgates<<<dim3(GG / 128, (QQ * NN) / 128), 256>>>(W_ih, b_ih, b_hh);

    int smem5 = (NN * HTS2 + CC * WTS3 + NN * REDS + 32 * 64) * sizeof(float);
    cudaFuncSetAttribute(k5_lstm, cudaFuncAttributeMaxDynamicSharedMemorySize, smem5);
    k5_lstm<<<NB5, 256, smem5>>>(W_hh);

    k6_lndec<<<(QQ * NN + 7) / 8, 256>>>(lng, lnb, W_dec, b_dec, out);
}

// round 12
// speedup vs baseline: 1.3141x; 1.3141x over previous
#include <cuda_runtime.h>
#include <math.h>

#define SS 512
#define NN 64
#define CC 512
#define QQ 256
#define VV 10
#define GG 2048
#define NB5 128
#define HTS2 516   // hts [n][k] stride
#define WTS2 24    // wts [k][gi] stride

__device__ float g_a0[SS * NN];
__device__ float g_a1[SS * NN];
__device__ float g_A[(size_t)NN * SS * QQ];
__device__ float g_queue[(size_t)QQ * NN * CC];
__device__ float g_xg[(size_t)QQ * NN * GG];
__device__ float g_gh[2 * NN * CC];               // h (tf32-rounded) [buf][n][k]
__device__ float g_hs[(size_t)QQ * NN * CC];
__device__ unsigned g_barcnt;

// ---------------- tf32 helpers ----------------
__device__ __forceinline__ float to_tf32(float x) {
    unsigned r;
    asm("cvt.rna.tf32.f32 %0, %1;" : "=r"(r) : "f"(x));
    return __uint_as_float(r);
}
__device__ __forceinline__ void mma_tf32(float& d0, float& d1, float& d2, float& d3,
                                         float a0, float a1, float a2, float a3,
                                         float b0, float b1) {
    asm volatile(
        "mma.sync.aligned.m16n8k8.row.col.f32.tf32.tf32.f32 "
        "{%0,%1,%2,%3},{%4,%5,%6,%7},{%8,%9},{%0,%1,%2,%3};"
        : "+f"(d0), "+f"(d1), "+f"(d2), "+f"(d3)
        : "r"(__float_as_uint(a0)), "r"(__float_as_uint(a1)),
          "r"(__float_as_uint(a2)), "r"(__float_as_uint(a3)),
          "r"(__float_as_uint(b0)), "r"(__float_as_uint(b1)));
}

// ---------------- K1: action softmax ----------------
__global__ void k1_actions(const float* __restrict__ memory,
                           const float* __restrict__ W_act,
                           const float* __restrict__ b_act) {
    int warp = blockIdx.x * (blockDim.x >> 5) + (threadIdx.x >> 5);
    int lane = threadIdx.x & 31;
    if (warp >= SS * NN) return;
    const float* row = memory + (size_t)warp * CC;
    float z0 = 0.f, z1 = 0.f;
    for (int c = lane; c < CC; c += 32) {
        float m = row[c];
        z0 += m * W_act[2 * c];
        z1 += m * W_act[2 * c + 1];
    }
#pragma unroll
    for (int o = 16; o; o >>= 1) {
        z0 += __shfl_down_sync(0xffffffffu, z0, o);
        z1 += __shfl_down_sync(0xffffffffu, z1, o);
    }
    if (lane == 0) {
        z0 += b_act[0]; z1 += b_act[1];
        float mx = fmaxf(z0, z1);
        float e0 = expf(z0 - mx), e1 = expf(z1 - mx);
        float inv = 1.f / (e0 + e1);
        g_a0[warp] = e0 * inv;
        g_a1[warp] = e1 * inv;
    }
}

// ---------------- K2: posvec recurrence ----------------
__global__ void k2_posvec() {
    if (blockIdx.x == 0 && threadIdx.x == 0) g_barcnt = 0u;
    int n = blockIdx.x;
    int q = threadIdx.x;
    __shared__ float sp[QQ];
    __shared__ float sa0[SS], sa1[SS];
    for (int s = q; s < SS; s += QQ) {
        sa0[s] = g_a0[s * NN + n];
        sa1[s] = g_a1[s * NN + n];
    }
    __syncthreads();
    float p = (q == 0) ? 1.f : 0.f;
    float* An = g_A + (size_t)n * SS * QQ;
    for (int s = 0; s < SS; s++) {
        float a0 = sa0[s], a1 = sa1[s];
        An[(size_t)s * QQ + q] = p * a1;
        sp[q] = p;
        __syncthreads();
        float prev = sp[(q + QQ - 1) & (QQ - 1)];
        __syncthreads();
        p = p * a0 + prev * a1;
    }
}

// ---------------- K3: queue via tf32 mma ----------------
__global__ void __launch_bounds__(256) k3_queue(const float* __restrict__ memory) {
    __shared__ float As[128 * 17];   // [q][s]
    __shared__ float Bs[64 * 17];    // [c][s]
    int n = blockIdx.z;
    int q0 = blockIdx.y * 128;
    int c0 = blockIdx.x * 64;
    int tid = threadIdx.x;
    int warp = tid >> 5, lane = tid & 31;
    int wm = warp >> 1, wn = warp & 1;
    int lr = lane >> 2, lc = lane & 3;

    float c[2][4][4];
#pragma unroll
    for (int a = 0; a < 2; a++)
#pragma unroll
        for (int b = 0; b < 4; b++)
#pragma unroll
            for (int d = 0; d < 4; d++) c[a][b][d] = 0.f;

    const float* Abase = g_A + (size_t)n * SS * QQ + q0;
    const float* Bbase = memory + (size_t)n * CC + c0;

    for (int s0 = 0; s0 < SS; s0 += 16) {
#pragma unroll
        for (int l = 0; l < 2; l++) {
            int f = tid + l * 256;
            int s = f >> 5, q4 = (f & 31) * 4;
            float4 v = *(const float4*)&Abase[(size_t)(s0 + s) * QQ + q4];
            As[(q4 + 0) * 17 + s] = to_tf32(v.x);
            As[(q4 + 1) * 17 + s] = to_tf32(v.y);
            As[(q4 + 2) * 17 + s] = to_tf32(v.z);
            As[(q4 + 3) * 17 + s] = to_tf32(v.w);
        }
        {
            int s = tid >> 4, c4 = (tid & 15) * 4;
            float4 v = *(const float4*)&Bbase[(size_t)(s0 + s) * NN * CC + c4];
            Bs[(c4 + 0) * 17 + s] = to_tf32(v.x);
            Bs[(c4 + 1) * 17 + s] = to_tf32(v.y);
            Bs[(c4 + 2) * 17 + s] = to_tf32(v.z);
            Bs[(c4 + 3) * 17 + s] = to_tf32(v.w);
        }
        __syncthreads();
#pragma unroll
        for (int ks = 0; ks < 2; ks++) {
            int k0 = ks * 8;
            float a[2][4];
#pragma unroll
            for (int tm = 0; tm < 2; tm++) {
                int row = wm * 32 + tm * 16 + lr;
                a[tm][0] = As[row * 17 + k0 + lc];
                a[tm][1] = As[(row + 8) * 17 + k0 + lc];
                a[tm][2] = As[row * 17 + k0 + lc + 4];
                a[tm][3] = As[(row + 8) * 17 + k0 + lc + 4];
            }
#pragma unroll
            for (int tn = 0; tn < 4; tn++) {
                int col = wn * 32 + tn * 8 + lr;
                float b0 = Bs[col * 17 + k0 + lc];
                float b1 = Bs[col * 17 + k0 + lc + 4];
#pragma unroll
                for (int tm = 0; tm < 2; tm++)
                    mma_tf32(c[tm][tn][0], c[tm][tn][1], c[tm][tn][2], c[tm][tn][3],
                             a[tm][0], a[tm][1], a[tm][2], a[tm][3], b0, b1);
            }
        }
        __syncthreads();
    }
#pragma unroll
    for (int tm = 0; tm < 2; tm++) {
#pragma unroll
        for (int tn = 0; tn < 4; tn++) {
            int cc = c0 + wn * 32 + tn * 8 + lc * 2;
            int r0 = q0 + wm * 32 + tm * 16 + lr;
            *(float2*)&g_queue[((size_t)r0 * NN + n) * CC + cc] =
                make_float2(c[tm][tn][0], c[tm][tn][1]);
            *(float2*)&g_queue[((size_t)(r0 + 8) * NN + n) * CC + cc] =
                make_float2(c[tm][tn][2], c[tm][tn][3]);
        }
    }
}

// ---------------- K4: xg = queue @ W_ih^T via tf32 mma.sync ----------------
__global__ void __launch_bounds__(256) k4_xgates(const float* __restrict__ W_ih,
                                                 const float* __restrict__ b_ih,
                                                 const float* __restrict__ b_hh) {
    __shared__ __align__(16) float As[128 * 20];
    __shared__ __align__(16) float Bs[128 * 20];
    int tid = threadIdx.x;
    int m0 = blockIdx.y * 128, g0 = blockIdx.x * 128;
    int warp = tid >> 5, lane = tid & 31;
    int wm = warp >> 1, wn = warp & 1;
    int lr = lane >> 2, lc = lane & 3;

    float c[2][8][4];
#pragma unroll
    for (int a = 0; a < 2; a++)
#pragma unroll
        for (int b = 0; b < 8; b++)
#pragma unroll
            for (int d = 0; d < 4; d++) c[a][b][d] = 0.f;

    int sr = tid >> 2;
    int sk = (tid & 3) * 4;
    const float* Ag = g_queue + (size_t)(m0 + sr) * CC + sk;
    const float* Bg = W_ih + (size_t)(g0 + sr) * CC + sk;

    float4 ra0 = *(const float4*)Ag;
    float4 ra1 = *(const float4*)(Ag + (size_t)64 * CC);
    float4 rb0 = *(const float4*)Bg;
    float4 rb1 = *(const float4*)(Bg + (size_t)64 * CC);

    for (int kt = 0; kt < 32; kt++) {
        *(float4*)&As[sr * 20 + sk] =
            make_float4(to_tf32(ra0.x), to_tf32(ra0.y), to_tf32(ra0.z), to_tf32(ra0.w));
        *(float4*)&As[(sr + 64) * 20 + sk] =
            make_float4(to_tf32(ra1.x), to_tf32(ra1.y), to_tf32(ra1.z), to_tf32(ra1.w));
        *(float4*)&Bs[sr * 20 + sk] =
            make_float4(to_tf32(rb0.x), to_tf32(rb0.y), to_tf32(rb0.z), to_tf32(rb0.w));
        *(float4*)&Bs[(sr + 64) * 20 + sk] =
            make_float4(to_tf32(rb1.x), to_tf32(rb1.y), to_tf32(rb1.z), to_tf32(rb1.w));
        __syncthreads();
        if (kt < 31) {
            int off = (kt + 1) * 16;
            ra0 = *(const float4*)(Ag + off);
            ra1 = *(const float4*)(Ag + (size_t)64 * CC + off);
            rb0 = *(const float4*)(Bg + off);
            rb1 = *(const float4*)(Bg + (size_t)64 * CC + off);
        }
#pragma unroll
        for (int s = 0; s < 2; s++) {
            int k0 = s * 8;
            float a[2][4];
#pragma unroll
            for (int tm = 0; tm < 2; tm++) {
                int row = wm * 32 + tm * 16 + lr;
                a[tm][0] = As[row * 20 + k0 + lc];
                a[tm][1] = As[(row + 8) * 20 + k0 + lc];
                a[tm][2] = As[row * 20 + k0 + lc + 4];
                a[tm][3] = As[(row + 8) * 20 + k0 + lc + 4];
            }
#pragma unroll
            for (int tn = 0; tn < 8; tn++) {
                int col = wn * 64 + tn * 8 + lr;
                float b0 = Bs[col * 20 + k0 + lc];
                float b1 = Bs[col * 20 + k0 + lc + 4];
#pragma unroll
                for (int tm = 0; tm < 2; tm++)
                    mma_tf32(c[tm][tn][0], c[tm][tn][1], c[tm][tn][2], c[tm][tn][3],
                             a[tm][0], a[tm][1], a[tm][2], a[tm][3], b0, b1);
            }
        }
        __syncthreads();
    }
#pragma unroll
    for (int tm = 0; tm < 2; tm++) {
#pragma unroll
        for (int tn = 0; tn < 8; tn++) {
            int g = g0 + wn * 64 + tn * 8 + lc * 2;
            float bv0 = b_ih[g] + b_hh[g];
            float bv1 = b_ih[g + 1] + b_hh[g + 1];
            int r0 = m0 + wm * 32 + tm * 16 + lr;
            float2 v0 = make_float2(c[tm][tn][0] + bv0, c[tm][tn][1] + bv1);
            float2 v1 = make_float2(c[tm][tn][2] + bv0, c[tm][tn][3] + bv1);
            *(float2*)&g_xg[(size_t)r0 * GG + g] = v0;
            *(float2*)&g_xg[(size_t)(r0 + 8) * GG + g] = v1;
        }
    }
}

// ---------------- K5: persistent LSTM (R7 config + distributed activation) ----------------
__device__ __forceinline__ float sigf(float x) { return 1.f / (1.f + expf(-x)); }

__device__ __forceinline__ void gridbar(unsigned target) {
    if (threadIdx.x == 0) {
        __threadfence();
        atomicAdd(&g_barcnt, 1u);
        while (*(volatile unsigned*)&g_barcnt < target) __nanosleep(32);
        __threadfence();
    }
    __syncthreads();
}

__global__ void __launch_bounds__(256, 1) k5_lstm(const float* __restrict__ W_hh) {
    extern __shared__ float sm[];
    float* hts = sm;                       // [64][HTS2]  h as [n][k] (tf32 values)
    float* wts = sm + NN * HTS2;           // [512][WTS2] W as [k][gi] (tf32 values)
    float* red = wts + CC * WTS2;          // [4][256]    K-half reduction
    float* gsm = red + 4 * 256;            // [16][64]    gates [gi][n]
    int tid = threadIdx.x;
    int b = blockIdx.x;
    int c0 = b * 4;
    int wid = tid >> 5, lane = tid & 31;
    int mt = wid & 3, kh = wid >> 2;       // m-tile 0..3, K-half 0..1
    int gid = lane >> 2, tig = lane & 3;
    int an = tid & 63, aj = tid >> 6;      // activation ownership: (n, j)

    // preload W slice as tf32 into wts[k][gi], gi = gate*4 + j
    {
        int gi = tid >> 4;                 // 0..15
        int gate = gi >> 2, j = gi & 3;
        const float* wrow = W_hh + (size_t)(gate * CC + c0 + j) * CC;
        int kc = (tid & 15) * 32;
#pragma unroll
        for (int u = 0; u < 8; u++) {
            float4 v = *(const float4*)&wrow[kc + u * 4];
            wts[(kc + u * 4 + 0) * WTS2 + gi] = to_tf32(v.x);
            wts[(kc + u * 4 + 1) * WTS2 + gi] = to_tf32(v.y);
            wts[(kc + u * 4 + 2) * WTS2 + gi] = to_tf32(v.z);
            wts[(kc + u * 4 + 3) * WTS2 + gi] = to_tf32(v.w);
        }
    }
    if (tid < 64) {
        *(float4*)&g_gh[tid * CC + c0] = make_float4(0.f, 0.f, 0.f, 0.f);
    }
    __syncthreads();
    unsigned u = 1;
    gridbar(u * NB5); u++;

    float creg = 0.f;                      // c state for (an, aj)

    for (int step = 0; step < QQ; step++) {
        int par = step & 1;
        const float* hb = g_gh + par * (NN * CC);

        // prefetch this thread's input-gate x values: gates 0..3 at (an, c0+aj)
        float xv0, xv1, xv2, xv3;
        {
            const float* xb = g_xg + ((size_t)step * NN + an) * GG + c0 + aj;
            xv0 = xb[0];
            xv1 = xb[512];
            xv2 = xb[1024];
            xv3 = xb[1536];
        }
        // stage h [n][k] into smem (values already tf32-rounded at write)
#pragma unroll
        for (int it = 0; it < 32; it++) {
            int f = tid + it * 256;        // float4 slot 0..8191
            int n = f >> 7;
            int k4 = (f & 127) * 4;
            float4 v = __ldcg((const float4*)&hb[n * CC + k4]);
            *(float4*)&hts[n * HTS2 + k4] = v;
        }
        __syncthreads();

        // tensor GEMM: gates[64n x 16gi] = h[64x512] @ Wt[512x16]
        float c[2][4];
#pragma unroll
        for (int nt = 0; nt < 2; nt++)
#pragma unroll
            for (int i = 0; i < 4; i++) c[nt][i] = 0.f;
        const float* Ab = &hts[(mt * 16) * HTS2 + kh * 256];
        const float* Bb = &wts[(kh * 256) * WTS2];
#pragma unroll 4
        for (int kc = 0; kc < 32; kc++) {
            int k0 = kc * 8;
            float a0 = Ab[gid * HTS2 + k0 + tig];
            float a1 = Ab[(gid + 8) * HTS2 + k0 + tig];
            float a2 = Ab[gid * HTS2 + k0 + tig + 4];
            float a3 = Ab[(gid + 8) * HTS2 + k0 + tig + 4];
#pragma unroll
            for (int nt = 0; nt < 2; nt++) {
                float b0 = Bb[(k0 + tig) * WTS2 + nt * 8 + gid];
                float b1 = Bb[(k0 + tig + 4) * WTS2 + nt * 8 + gid];
                mma_tf32(c[nt][0], c[nt][1], c[nt][2], c[nt][3],
                         a0, a1, a2, a3, b0, b1);
            }
        }
        // K-half reduction
        if (kh == 1) {
#pragma unroll
            for (int nt = 0; nt < 2; nt++) {
                *(float4*)&red[mt * 256 + nt * 128 + lane * 4] =
                    make_float4(c[nt][0], c[nt][1], c[nt][2], c[nt][3]);
            }
        }
        __syncthreads();
        if (kh == 0) {
#pragma unroll
            for (int nt = 0; nt < 2; nt++) {
                float4 r = *(const float4*)&red[mt * 256 + nt * 128 + lane * 4];
                c[nt][0] += r.x; c[nt][1] += r.y; c[nt][2] += r.z; c[nt][3] += r.w;
                int n0 = mt * 16 + gid;
                int gi0 = nt * 8 + tig * 2;
                gsm[gi0 * 64 + n0] = c[nt][0];
                gsm[(gi0 + 1) * 64 + n0] = c[nt][1];
                gsm[gi0 * 64 + n0 + 8] = c[nt][2];
                gsm[(gi0 + 1) * 64 + n0 + 8] = c[nt][3];
            }
        }
        __syncthreads();

        // distributed activation: thread (an, aj) handles one column
        {
            float iv = gsm[(0 * 4 + aj) * 64 + an] + xv0;
            float fv = gsm[(1 * 4 + aj) * 64 + an] + xv1;
            float gv = gsm[(2 * 4 + aj) * 64 + an] + xv2;
            float ov = gsm[(3 * 4 + aj) * 64 + an] + xv3;
            float cc = sigf(fv) * creg + sigf(iv) * tanhf(gv);
            creg = cc;
            float h = sigf(ov) * tanhf(cc);
            int nxt = (step + 1) & 1;
            g_gh[nxt * (NN * CC) + an * CC + c0 + aj] = to_tf32(h);
            g_hs[((size_t)step * NN + an) * CC + c0 + aj] = h;
        }
        __syncthreads();
        gridbar(u * NB5); u++;
    }
}

// ---------------- K6: LayerNorm + decode ----------------
__global__ void k6_lndec(const float* __restrict__ gamma,
                         const float* __restrict__ beta,
                         const float* __restrict__ W_dec,
                         const float* __restrict__ b_dec,
                         float* __restrict__ out) {
    __shared__ float sW[CC * VV];
    __shared__ float sG[CC], sB[CC], sbd[VV];
    int tid = threadIdx.x;
    for (int i = tid; i < CC * VV; i += 256) sW[i] = W_dec[i];
    for (int i = tid; i < CC; i += 256) { sG[i] = gamma[i]; sB[i] = beta[i]; }
    if (tid < VV) sbd[tid] = b_dec[tid];
    __syncthreads();

    int warp = blockIdx.x * 8 + (tid >> 5);
    int lane = tid & 31;
    if (warp >= QQ * NN) return;
    const float* row = g_hs + (size_t)warp * CC;

    float x[16];
    float s = 0.f, s2 = 0.f;
#pragma unroll
    for (int t = 0; t < 4; t++) {
        float4 v = *(const float4*)&row[lane * 4 + t * 128];
        x[t * 4 + 0] = v.x; x[t * 4 + 1] = v.y; x[t * 4 + 2] = v.z; x[t * 4 + 3] = v.w;
        s += v.x + v.y + v.z + v.w;
        s2 += v.x * v.x + v.y * v.y + v.z * v.z + v.w * v.w;
    }
#pragma unroll
    for (int o = 16; o; o >>= 1) {
        s += __shfl_xor_sync(0xffffffffu, s, o);
        s2 += __shfl_xor_sync(0xffffffffu, s2, o);
    }
    float mu = s * (1.f / CC);
    float var = s2 * (1.f / CC) - mu * mu;
    float rs = rsqrtf(var + 1e-5f);

    float acc[VV];
#pragma unroll
    for (int v = 0; v < VV; v++) acc[v] = 0.f;
#pragma unroll
    for (int t = 0; t < 4; t++) {
#pragma unroll
        for (int e = 0; e < 4; e++) {
            int c = lane * 4 + t * 128 + e;
            float nv = (x[t * 4 + e] - mu) * rs * sG[c] + sB[c];
#pragma unroll
            for (int v = 0; v < VV; v++) acc[v] = fmaf(nv, sW[c * VV + v], acc[v]);
        }
    }
#pragma unroll
    for (int v = 0; v < VV; v++) {
        float a = acc[v];
#pragma unroll
        for (int o = 16; o; o >>= 1) a += __shfl_xor_sync(0xffffffffu, a, o);
        if (lane == 0) out[(size_t)warp * VV + v] = a + sbd[v];
    }
}

extern "C" void kernel_launch(void* const* d_in, const int* in_sizes, int n_in,
                              void* d_out, int out_size) {
    const float* memory = (const float*)d_in[0];
    const float* W_act  = (const float*)d_in[1];
    const float* b_act  = (const float*)d_in[2];
    const float* W_ih   = (const float*)d_in[3];
    const float* W_hh   = (const float*)d_in[4];
    const float* b_ih   = (const float*)d_in[5];
    const float* b_hh   = (const float*)d_in[6];
    const float* lng    = (const float*)d_in[7];
    const float* lnb    = (const float*)d_in[8];
    const float* W_dec  = (const float*)d_in[9];
    const float* b_dec  = (const float*)d_in[10];
    float* out = (float*)d_out;

    k1_actions<<<(SS * NN + 7) / 8, 256>>>(memory, W_act, b_act);
    k2_posvec<<<NN, QQ>>>();
    k3_queue<<<dim3(CC / 64, QQ / 128, NN), 256>>>(memory);
    k4_xgates<<<dim3(GG / 128, (QQ * NN) / 128), 256>>>(W_ih, b_ih, b_hh);

    int smem5 = (NN * HTS2 + CC * WTS2 + 4 * 256 + 16 * 64) * sizeof(float);
    cudaFuncSetAttribute(k5_lstm, cudaFuncAttributeMaxDynamicSharedMemorySize, smem5);
    k5_lstm<<<NB5, 256, smem5>>>(W_hh);

    k6_lndec<<<(QQ * NN + 7) / 8, 256>>>(lng, lnb, W_dec, b_dec, out);
}